// round 15
// baseline (speedup 1.0000x reference)
#include <cuda_runtime.h>
#include <math.h>

#define PI_D 3.14159265358979323846
#define SCALE (1.0f/131072.0f)   // 1/(64*64*32)

// Fill-region mapping: out==0 exactly for X in [16,64). Per batch (2,097,152
// float4 total) the region is [524288, 2097152) = 1,572,864 float4. A global
// fill index g in [0, 6291456) maps to batch g/1572864, offset g%1572864.
#define FILL_PER_B 1572864
#define OUT_PER_B  2097152
#define FILL_OFF   524288

// kA dynamic smem partition (floats):
//   sx: [0, 33280)         64 rows x 520 (64 z x 8 c + pad 8)
//   t1: [33280, 50688)     64*136 float2
//   tw: [50688, 50816)     64 float2
#define KA_SMEM_BYTES 203264

// Intermediates: m = Xs*256 + ky*16 + kz  (matches weight mode layout)
__device__ float2 g_A2[4*4096*32];   // [b][m][c]  after forward z,y DFT
__device__ float2 g_A5[4*4096*32];   // [b][m][c]  after c-DFT + mix + inv o-DFT

__device__ __forceinline__ float4* fill_ptr(float* out, long g0, int t) {
    long bf  = g0 / FILL_PER_B;
    long off = g0 - bf * FILL_PER_B;
    return (float4*)out + bf*OUT_PER_B + FILL_OFF + off + t;
}

// ============================================================================
// Kernel A: forward DFT over z (64->16) and y (64->16), radix-4 decimated.
// Block = (b, Xs, cg of 8 channels), 1024 threads, x-slab staged in dynamic
// smem (coalesced float4 load) so the par-split costs no extra DRAM traffic.
// Stage 1: thread = (c, y, par); par=0 -> kz residues {0,2}, par=1 -> {1,3};
// 16 accumulator floats/thread -> regs <= 64 -> 32 warps/SM.
// Carries 50% of the zero-fill (12 STG.128/thread) interleaved into stage 1.
// tw[n] = (cos, sin)(2 pi n / 64); e^{-i th} = (cw, -sw).
// ============================================================================
__global__ __launch_bounds__(1024) void kA(const float* __restrict__ x,
                                           float* __restrict__ out) {
    extern __shared__ float sm[];
    float*  sx = sm;                       // [y*520 + z*8 + c]
    float2* t1 = (float2*)(sm + 33280);    // [y][kz*8+c], row pad 128->136
    float2* tw = (float2*)(sm + 50688);
    int bid = blockIdx.x;                  // b*64 + Xs*4 + cg
    int cg = bid & 3;
    int Xs = (bid >> 2) & 15;
    int b  = bid >> 6;
    int t = threadIdx.x;
    if (t < 64) {
        double ang = 2.0*PI_D*(double)t/64.0;
        tw[t] = make_float2((float)cos(ang), (float)sin(ang));
    }

    // ---- stage 0: coalesced slab load: x[b][Xs][y][z][cg*8..cg*8+8) -> sx.
    {
        const float4* xg = (const float4*)x + (size_t)(b*64 + Xs)*32768 + cg*2;
        #pragma unroll
        for (int k = 0; k < 8; k++) {
            int i = t + k*1024;
            int y = i >> 7, rem = i & 127, z = rem >> 1, h = rem & 1;
            float4 v = xg[(size_t)y*512 + z*8 + h];
            *(float4*)&sx[y*520 + z*8 + h*4] = v;
        }
    }
    __syncthreads();

    // fill share: blocks 0..255 cover g in [0, 3145728), 12288 f4/block
    float4* zp = fill_ptr(out, (long)bid * 12288, t);
    const float4 z4 = make_float4(0.f, 0.f, 0.f, 0.f);

    // ---- stage 1: z-DFT (64 -> 16), radix-4, par-split. thread = (c, y, par).
    {
        int c = t & 7, y = (t >> 3) & 63, par = t >> 9;   // par warp-uniform
        const float* srow = sx + y*520 + c;
        float er[4], ei[4], fr[4], fi[4];
        #pragma unroll
        for (int m=0;m<4;m++){er[m]=ei[m]=fr[m]=fi[m]=0.f;}
        #pragma unroll
        for (int z0 = 0; z0 < 16; z0++) {
            float v0 = srow[(z0   )*8];
            float v1 = srow[(z0+16)*8];
            float v2 = srow[(z0+32)*8];
            float v3 = srow[(z0+48)*8];
            if (z0 < 12) zp[z0*1024] = z4;   // interleaved fill (12 total)
            if (par == 0) {
                float e02=v0+v2, e13=v1+v3;
                float s=e02+e13, d=e02-e13;
                #pragma unroll
                for (int m=0;m<4;m++) {
                    { float2 w = tw[((4*m  )*z0)&63]; er[m]+=s*w.x; ei[m]-=s*w.y; }
                    { float2 w = tw[((4*m+2)*z0)&63]; fr[m]+=d*w.x; fi[m]-=d*w.y; }
                }
            } else {
                float p=v0-v2, q=v1-v3;
                #pragma unroll
                for (int m=0;m<4;m++) {
                    { float2 w = tw[((4*m+1)*z0)&63];
                      er[m]+=p*w.x - q*w.y; ei[m]-=p*w.y + q*w.x; }
                    { float2 w = tw[((4*m+3)*z0)&63];
                      fr[m]+=p*w.x + q*w.y; fi[m]+=q*w.x - p*w.y; }
                }
            }
        }
        #pragma unroll
        for (int m=0;m<4;m++){
            t1[y*136 + (4*m +     par)*8 + c] = make_float2(er[m], ei[m]);
            t1[y*136 + (4*m + 2 + par)*8 + c] = make_float2(fr[m], fi[m]);
        }
    }
    __syncthreads();

    // ---- stage 2: y-DFT (64 -> 16), radix-4. thread = (c, kz, r, mh).
    {
        int c = t & 7, kz = (t >> 3) & 15, r = (t >> 7) & 3, mh = t >> 9;
        int ma = 2*mh, mbv = 2*mh + 1;
        float ar0=0.f, ai0=0.f, ar1=0.f, ai1=0.f;
        #pragma unroll
        for (int y0 = 0; y0 < 16; y0++) {
            float2 a0 = t1[(y0   )*136 + kz*8 + c];
            float2 a1 = t1[(y0+16)*136 + kz*8 + c];
            float2 a2 = t1[(y0+32)*136 + kz*8 + c];
            float2 a3 = t1[(y0+48)*136 + kz*8 + c];
            float2 u;
            if (r == 0)      u = make_float2(a0.x+a1.x+a2.x+a3.x, a0.y+a1.y+a2.y+a3.y);
            else if (r == 2) u = make_float2(a0.x-a1.x+a2.x-a3.x, a0.y-a1.y+a2.y-a3.y);
            else {
                float pr=a0.x-a2.x, pi=a0.y-a2.y, qr=a1.x-a3.x, qi=a1.y-a3.y;
                if (r == 1) u = make_float2(pr+qi, pi-qr);   // p - i q
                else        u = make_float2(pr-qi, pi+qr);   // p + i q
            }
            { float2 w = tw[((4*ma +r)*y0)&63];
              ar0 += u.x*w.x + u.y*w.y; ai0 += u.y*w.x - u.x*w.y; }
            { float2 w = tw[((4*mbv+r)*y0)&63];
              ar1 += u.x*w.x + u.y*w.y; ai1 += u.y*w.x - u.x*w.y; }
        }
        float2* dst = g_A2 + ((size_t)(b*4096 + Xs*256 + kz))*32 + cg*8 + c;
        dst[(size_t)(4*ma +r)*512] = make_float2(ar0, ai0);
        dst[(size_t)(4*mbv+r)*512] = make_float2(ar1, ai1);
    }
}

// ============================================================================
// Kernel B: per 16-mode chunk (all 4 batches): c-DFT -> 32x32 mix -> inv o-DFT
// Stages 1 & 3 radix-4. Carries 17% of the zero-fill (8 STG.128/thread).
// ============================================================================
__global__ __launch_bounds__(512, 2) void kB(const float* __restrict__ wr_g,
                                             const float* __restrict__ wi_g,
                                             float* __restrict__ out) {
    __shared__ float2 sA[64*33];      // [(b*16+ml)][c], pad 33
    __shared__ float2 sF[64*33];      // [(b*16+ml)][i], pad 33
    __shared__ float2 sG[64*33];      // [(b*16+ml)][o], pad 33
    __shared__ float2 tw[32];
    int m0 = blockIdx.x * 16;
    int t = threadIdx.x;
    if (t < 32) {
        double ang = 2.0*PI_D*(double)t/32.0;
        tw[t] = make_float2((float)cos(ang), (float)sin(ang));
    }
    #pragma unroll
    for (int r = 0; r < 4; r++) {
        int idx = t + r*512;                    // (b_, ml, c), c fastest
        int b_ = idx >> 9, rem = idx & 511;
        int ml = rem >> 5, c = rem & 31;
        sA[(b_*16 + ml)*33 + c] = g_A2[((size_t)(b_*4096 + m0 + ml))*32 + c];
    }
    __syncthreads();

    // fill share: g in [3145728, 4194304), 4096 f4/block
    float4* zp = fill_ptr(out, 3145728L + (long)blockIdx.x * 4096, t);
    const float4 z4 = make_float4(0.f, 0.f, 0.f, 0.f);

    // stage 1: forward DFT over c (32 -> 32), radix-4.
    {
        int r = t & 3, ml = (t >> 2) & 15, b = (t >> 6) & 3, mqh = t >> 8;
        const float2* arow = sA + (b*16 + ml)*33;
        float fr[4], fi[4];
        #pragma unroll
        for (int k=0;k<4;k++){fr[k]=0.f; fi[k]=0.f;}
        #pragma unroll
        for (int c0 = 0; c0 < 8; c0++) {
            zp[c0*512] = z4;                     // interleaved fill (8 total)
            float2 a0 = arow[c0], a1 = arow[c0+8], a2 = arow[c0+16], a3 = arow[c0+24];
            float2 u;
            if (r == 0)      u = make_float2(a0.x+a1.x+a2.x+a3.x, a0.y+a1.y+a2.y+a3.y);
            else if (r == 2) u = make_float2(a0.x-a1.x+a2.x-a3.x, a0.y-a1.y+a2.y-a3.y);
            else {
                float pr=a0.x-a2.x, pi=a0.y-a2.y, qr=a1.x-a3.x, qi=a1.y-a3.y;
                if (r == 1) u = make_float2(pr+qi, pi-qr);   // p - i q
                else        u = make_float2(pr-qi, pi+qr);   // p + i q
            }
            #pragma unroll
            for (int k=0;k<4;k++) {
                int i = 4*(mqh*4 + k) + r;
                float2 w = tw[(i*c0) & 31];      // e^{-i}: u*(cw - i sw)
                fr[k] += u.x*w.x + u.y*w.y;
                fi[k] += u.y*w.x - u.x*w.y;
            }
        }
        float2* frow = sF + (b*16 + ml)*33;
        #pragma unroll
        for (int k=0;k<4;k++)
            frow[4*(mqh*4 + k) + r] = make_float2(fr[k], fi[k]);
    }
    __syncthreads();

    // stage 2: channel mix. thread = (ml, o); weights loaded once, 4 b reuse.
    {
        int ml = t & 15, o = t >> 4;
        float r0=0,i0=0,r1=0,i1=0,r2=0,i2=0,r3=0,i3=0;
        const float* wrp = wr_g + (size_t)o*4096 + m0 + ml;
        const float* wip = wi_g + (size_t)o*4096 + m0 + ml;
        #pragma unroll 2
        for (int i = 0; i < 32; i++) {
            float wr = wrp[(size_t)i*131072];
            float wi = wip[(size_t)i*131072];
            float2 f0 = sF[( 0 + ml)*33 + i];
            float2 f1 = sF[(16 + ml)*33 + i];
            float2 f2 = sF[(32 + ml)*33 + i];
            float2 f3 = sF[(48 + ml)*33 + i];
            r0 += f0.x*wr - f0.y*wi;  i0 += f0.x*wi + f0.y*wr;
            r1 += f1.x*wr - f1.y*wi;  i1 += f1.x*wi + f1.y*wr;
            r2 += f2.x*wr - f2.y*wi;  i2 += f2.x*wi + f2.y*wr;
            r3 += f3.x*wr - f3.y*wi;  i3 += f3.x*wi + f3.y*wr;
        }
        sG[( 0 + ml)*33 + o] = make_float2(r0, i0);
        sG[(16 + ml)*33 + o] = make_float2(r1, i1);
        sG[(32 + ml)*33 + o] = make_float2(r2, i2);
        sG[(48 + ml)*33 + o] = make_float2(r3, i3);
    }
    __syncthreads();

    // stage 3: inverse DFT over o -> c (32 -> 32), radix-4, scaled.
    {
        int r = t & 3, ml = (t >> 2) & 15, b = (t >> 6) & 3, mqh = t >> 8;
        const float2* grow = sG + (b*16 + ml)*33;
        float cr[4], ci[4];
        #pragma unroll
        for (int k=0;k<4;k++){cr[k]=0.f; ci[k]=0.f;}
        #pragma unroll
        for (int o0 = 0; o0 < 8; o0++) {
            float2 g0 = grow[o0], g1 = grow[o0+8], g2 = grow[o0+16], g3 = grow[o0+24];
            float2 u;
            if (r == 0)      u = make_float2(g0.x+g1.x+g2.x+g3.x, g0.y+g1.y+g2.y+g3.y);
            else if (r == 2) u = make_float2(g0.x-g1.x+g2.x-g3.x, g0.y-g1.y+g2.y-g3.y);
            else {
                float pr=g0.x-g2.x, pi=g0.y-g2.y, qr=g1.x-g3.x, qi=g1.y-g3.y;
                if (r == 1) u = make_float2(pr-qi, pi+qr);   // p + i q
                else        u = make_float2(pr+qi, pi-qr);   // p - i q
            }
            #pragma unroll
            for (int k=0;k<4;k++) {
                int c = 4*(mqh*4 + k) + r;
                float2 w = tw[(c*o0) & 31];      // e^{+i}: u*(cw + i sw)
                cr[k] += u.x*w.x - u.y*w.y;
                ci[k] += u.x*w.y + u.y*w.x;
            }
        }
        float2* dst = g_A5 + ((size_t)(b*4096 + m0 + ml))*32;
        #pragma unroll
        for (int k=0;k<4;k++)
            dst[4*(mqh*4 + k) + r] = make_float2(cr[k]*SCALE, ci[k]*SCALE);
    }
}

// ============================================================================
// Kernel C: inverse DFT over ky (16->64) and kz (16->64 real), radix-4 output
// side. Block = (b, Xs, cg of 8 channels), 512 threads. Carries 33% of the
// zero-fill (16 STG.128/thread) in stage 2's yy-loop.
// ============================================================================
__global__ __launch_bounds__(512) void kC(float* __restrict__ out) {
    __shared__ float2 sIn[16*16*8];   // [ky][kz][c]
    __shared__ float2 t1[64*128];     // [y][kz*8+c]
    __shared__ float2 tw[64];
    int bid = blockIdx.x;             // b*64 + Xs*4 + cg
    int cg = bid & 3;
    int Xs = (bid >> 2) & 15;
    int b  = bid >> 6;
    int t = threadIdx.x;
    if (t < 64) {
        double ang = 2.0*PI_D*(double)t/64.0;
        tw[t] = make_float2((float)cos(ang), (float)sin(ang));
    }
    #pragma unroll
    for (int r = 0; r < 4; r++) {
        int idx = t + r*512;
        int c = idx & 7, kz = (idx >> 3) & 15, ky = idx >> 7;
        sIn[idx] = g_A5[((size_t)(b*4096 + Xs*256 + ky*16 + kz))*32 + cg*8 + c];
    }
    __syncthreads();

    // fill share: g in [4194304, 6291456), 8192 f4/block
    float4* zp = fill_ptr(out, 4194304L + (long)bid * 8192, t);
    const float4 z4 = make_float4(0.f, 0.f, 0.f, 0.f);

    // ---- stage 1: inverse ky-DFT (16 -> 64), output radix-4.
    {
        int c = t & 7, kz = (t >> 3) & 15, yq = t >> 7;
        float akr[16], aki[16];
        #pragma unroll
        for (int k = 0; k < 16; k++) {
            float2 a = sIn[(k*16 + kz)*8 + c];
            akr[k] = a.x; aki[k] = a.y;
        }
        #pragma unroll
        for (int j = 0; j < 4; j++) {
            int y0 = yq*4 + j;
            float Tr[4], Ti[4];
            #pragma unroll
            for (int r = 0; r < 4; r++) {
                float trr = 0.f, tii = 0.f;
                #pragma unroll
                for (int m = 0; m < 4; m++) {
                    int k = 4*m + r;
                    float2 w = tw[(k*y0)&63];    // e^{+i}
                    trr += akr[k]*w.x - aki[k]*w.y;
                    tii += akr[k]*w.y + aki[k]*w.x;
                }
                Tr[r] = trr; Ti[r] = tii;
            }
            float Er=Tr[0]+Tr[2], Ei=Ti[0]+Ti[2];
            float Fr=Tr[0]-Tr[2], Fi=Ti[0]-Ti[2];
            float Gr=Tr[1]+Tr[3], Gi=Ti[1]+Ti[3];
            float Hr=Tr[1]-Tr[3], Hi=Ti[1]-Ti[3];
            t1[(y0   )*128 + kz*8 + c] = make_float2(Er+Gr, Ei+Gi);  // p=0
            t1[(y0+16)*128 + kz*8 + c] = make_float2(Fr-Hi, Fi+Hr);  // p=1
            t1[(y0+32)*128 + kz*8 + c] = make_float2(Er-Gr, Ei-Gi);  // p=2
            t1[(y0+48)*128 + kz*8 + c] = make_float2(Fr+Hi, Fi-Hr);  // p=3
        }
    }
    __syncthreads();

    // ---- stage 2: inverse kz-DFT (16 -> 64), real part, output radix-4.
    {
        int c = t & 7, z0 = (t >> 3) & 15, yq = t >> 7;
        float cwv[16], swv[16];
        #pragma unroll
        for (int k = 0; k < 16; k++) {
            float2 w = tw[(k*z0)&63];
            cwv[k] = w.x; swv[k] = w.y;
        }
        float* dst = out + ((((size_t)b*64 + Xs)*64)*64)*32 + (size_t)z0*32 + cg*8 + c;
        for (int l = 0; l < 16; l++) {
            int yy = yq*16 + l;
            zp[l*512] = z4;                      // interleaved fill (16 total)
            float t0r=0.f, t2r=0.f, t1r=0.f, t1i=0.f, t3r=0.f, t3i=0.f;
            #pragma unroll
            for (int m = 0; m < 4; m++) {
                { int k=4*m;   float2 a=t1[yy*128+k*8+c]; t0r += a.x*cwv[k]-a.y*swv[k]; }
                { int k=4*m+2; float2 a=t1[yy*128+k*8+c]; t2r += a.x*cwv[k]-a.y*swv[k]; }
                { int k=4*m+1; float2 a=t1[yy*128+k*8+c]; t1r += a.x*cwv[k]-a.y*swv[k];
                                                          t1i += a.x*swv[k]+a.y*cwv[k]; }
                { int k=4*m+3; float2 a=t1[yy*128+k*8+c]; t3r += a.x*cwv[k]-a.y*swv[k];
                                                          t3i += a.x*swv[k]+a.y*cwv[k]; }
            }
            float t02p=t0r+t2r, t02m=t0r-t2r, t13p=t1r+t3r, h=t1i-t3i;
            size_t base = (size_t)yy*2048;
            dst[base        ] = t02p + t13p;   // z = z0
            dst[base +  512 ] = t02m - h;      // z = z0+16
            dst[base + 1024 ] = t02p - t13p;   // z = z0+32
            dst[base + 1536 ] = t02m + h;      // z = z0+48
        }
    }
}

extern "C" void kernel_launch(void* const* d_in, const int* in_sizes, int n_in,
                              void* d_out, int out_size) {
    const float* x  = (const float*)d_in[0];
    const float* wr = (const float*)d_in[1];
    const float* wi = (const float*)d_in[2];
    float* out = (float*)d_out;

    // Host-side attribute set (idempotent, capture-safe, no allocation).
    cudaFuncSetAttribute(kA, cudaFuncAttributeMaxDynamicSharedMemorySize,
                         KA_SMEM_BYTES);

    kA<<<256, 1024, KA_SMEM_BYTES>>>(x, out);  // fwd z,y DFT + 50% fill
    kB<<<256, 512>>>(wr, wi, out);             // c-DFT + mix + inv o-DFT + 17% fill
    kC<<<256, 512>>>(out);                     // inverse ky,kz DFT + 33% fill
}

// round 16
// speedup vs baseline: 1.0440x; 1.0440x over previous
#include <cuda_runtime.h>
#include <math.h>

#define PI_D 3.14159265358979323846
#define SCALE (1.0f/131072.0f)   // 1/(64*64*32)

// Fill-region mapping: out==0 exactly for X in [16,64). Per batch (2,097,152
// float4 total) the region is [524288, 2097152) = 1,572,864 float4. A global
// fill index g in [0, 6291456) maps to batch g/1572864, offset g%1572864.
#define FILL_PER_B 1572864
#define OUT_PER_B  2097152
#define FILL_OFF   524288

// Intermediates: m = Xs*256 + ky*16 + kz  (matches weight mode layout)
__device__ float2 g_A2[4*4096*32];   // [b][m][c]  after forward z,y DFT
__device__ float2 g_A5[4*4096*32];   // [b][m][c]  after c-DFT + mix + inv o-DFT

__device__ __forceinline__ float4* fill_ptr(float* out, long g0, int t) {
    long bf  = g0 / FILL_PER_B;
    long off = g0 - bf * FILL_PER_B;
    return (float4*)out + bf*OUT_PER_B + FILL_OFF + off + t;
}

// ============================================================================
// Kernel A: forward DFT over z (64->16) and y (64->16), radix-4 decimated.
// Block = (b, Xs, cg of 8 channels), 512 threads. Carries 50% of the
// zero-fill (24 STG.128/thread) interleaved into stage 1.
// tw[n] = (cos, sin)(2 pi n / 64); e^{-i th} = (cw, -sw).
// ============================================================================
__global__ __launch_bounds__(512) void kA(const float* __restrict__ x,
                                          float* __restrict__ out) {
    __shared__ float2 t1[64*136];     // [y][kz*8+c], row pad 128->136
    __shared__ float2 tw[64];
    int bid = blockIdx.x;             // b*64 + Xs*4 + cg
    int cg = bid & 3;
    int Xs = (bid >> 2) & 15;
    int b  = bid >> 6;
    int t = threadIdx.x;
    if (t < 64) {
        double ang = 2.0*PI_D*(double)t/64.0;
        tw[t] = make_float2((float)cos(ang), (float)sin(ang));
    }
    __syncthreads();

    // fill share: blocks 0..255 cover g in [0, 3145728), 12288 f4/block
    float4* zp = fill_ptr(out, (long)bid * 12288, t);
    const float4 z4 = make_float4(0.f, 0.f, 0.f, 0.f);

    // ---- stage 1: z-DFT (64 -> 16), radix-4. thread = (y, c).
    {
        int c = t & 7, y = t >> 3;
        const float* src = x + ((((size_t)b*64 + Xs)*64 + y)*64)*32 + cg*8 + c;
        float r0[4],i0[4],r1[4],i1[4],r2[4],i2[4],r3[4],i3[4];
        #pragma unroll
        for (int m=0;m<4;m++){r0[m]=i0[m]=r1[m]=i1[m]=r2[m]=i2[m]=r3[m]=i3[m]=0.f;}
        #pragma unroll
        for (int z0 = 0; z0 < 16; z0++) {
            float v0 = src[(z0   )*32];
            float v1 = src[(z0+16)*32];
            float v2 = src[(z0+32)*32];
            float v3 = src[(z0+48)*32];
            // interleaved fill: 2 stores for z0<8, 1 after (24 total)
            if (z0 < 8) {
                zp[(z0*2  )*512] = z4;
                zp[(z0*2+1)*512] = z4;
            } else {
                zp[(z0+8)*512] = z4;
            }
            float e02=v0+v2, e13=v1+v3;
            float s=e02+e13, d=e02-e13, p=v0-v2, q=v1-v3;
            #pragma unroll
            for (int m=0;m<4;m++) {
                { float2 w = tw[((4*m  )*z0)&63]; r0[m]+=s*w.x;         i0[m]-=s*w.y; }
                { float2 w = tw[((4*m+2)*z0)&63]; r2[m]+=d*w.x;         i2[m]-=d*w.y; }
                { float2 w = tw[((4*m+1)*z0)&63]; r1[m]+=p*w.x - q*w.y; i1[m]-=p*w.y + q*w.x; }
                { float2 w = tw[((4*m+3)*z0)&63]; r3[m]+=p*w.x + q*w.y; i3[m]+=q*w.x - p*w.y; }
            }
        }
        #pragma unroll
        for (int m=0;m<4;m++){
            t1[y*136 + (4*m  )*8 + c] = make_float2(r0[m], i0[m]);
            t1[y*136 + (4*m+1)*8 + c] = make_float2(r1[m], i1[m]);
            t1[y*136 + (4*m+2)*8 + c] = make_float2(r2[m], i2[m]);
            t1[y*136 + (4*m+3)*8 + c] = make_float2(r3[m], i3[m]);
        }
    }
    __syncthreads();

    // ---- stage 2: y-DFT (64 -> 16), radix-4. thread = (c, kz, residue r).
    {
        int c = t & 7, kz = (t >> 3) & 15, r = t >> 7;
        float ar[4], ai[4];
        #pragma unroll
        for (int m=0;m<4;m++){ar[m]=0.f; ai[m]=0.f;}
        #pragma unroll
        for (int y0 = 0; y0 < 16; y0++) {
            float2 a0 = t1[(y0   )*136 + kz*8 + c];
            float2 a1 = t1[(y0+16)*136 + kz*8 + c];
            float2 a2 = t1[(y0+32)*136 + kz*8 + c];
            float2 a3 = t1[(y0+48)*136 + kz*8 + c];
            float2 u;
            if (r == 0)      u = make_float2(a0.x+a1.x+a2.x+a3.x, a0.y+a1.y+a2.y+a3.y);
            else if (r == 2) u = make_float2(a0.x-a1.x+a2.x-a3.x, a0.y-a1.y+a2.y-a3.y);
            else {
                float pr=a0.x-a2.x, pi=a0.y-a2.y, qr=a1.x-a3.x, qi=a1.y-a3.y;
                if (r == 1) u = make_float2(pr+qi, pi-qr);   // p - i q
                else        u = make_float2(pr-qi, pi+qr);   // p + i q
            }
            #pragma unroll
            for (int m=0;m<4;m++) {
                int ky = 4*m + r;
                float2 w = tw[(ky*y0)&63];
                ar[m] += u.x*w.x + u.y*w.y;     // u * (cw - i sw)
                ai[m] += u.y*w.x - u.x*w.y;
            }
        }
        float2* dst = g_A2 + ((size_t)(b*4096 + Xs*256 + kz))*32 + cg*8 + c;
        #pragma unroll
        for (int m=0;m<4;m++)
            dst[(size_t)(4*m+r)*512] = make_float2(ar[m], ai[m]);
    }
}

// ============================================================================
// Kernel B: per 16-mode chunk (all 4 batches): c-DFT -> 32x32 mix -> inv o-DFT
// Stages 1 & 3 radix-4. Carries 17% of the zero-fill (8 STG.128/thread).
// ============================================================================
__global__ __launch_bounds__(512, 2) void kB(const float* __restrict__ wr_g,
                                             const float* __restrict__ wi_g,
                                             float* __restrict__ out) {
    __shared__ float2 sA[64*33];      // [(b*16+ml)][c], pad 33
    __shared__ float2 sF[64*33];      // [(b*16+ml)][i], pad 33
    __shared__ float2 sG[64*33];      // [(b*16+ml)][o], pad 33
    __shared__ float2 tw[32];
    int m0 = blockIdx.x * 16;
    int t = threadIdx.x;
    if (t < 32) {
        double ang = 2.0*PI_D*(double)t/32.0;
        tw[t] = make_float2((float)cos(ang), (float)sin(ang));
    }
    #pragma unroll
    for (int r = 0; r < 4; r++) {
        int idx = t + r*512;                    // (b_, ml, c), c fastest
        int b_ = idx >> 9, rem = idx & 511;
        int ml = rem >> 5, c = rem & 31;
        sA[(b_*16 + ml)*33 + c] = g_A2[((size_t)(b_*4096 + m0 + ml))*32 + c];
    }
    __syncthreads();

    // fill share: g in [3145728, 4194304), 4096 f4/block
    float4* zp = fill_ptr(out, 3145728L + (long)blockIdx.x * 4096, t);
    const float4 z4 = make_float4(0.f, 0.f, 0.f, 0.f);

    // stage 1: forward DFT over c (32 -> 32), radix-4.
    // thread = (r, ml, b, mqh); computes i = 4*(mqh*4+k) + r for k=0..3.
    {
        int r = t & 3, ml = (t >> 2) & 15, b = (t >> 6) & 3, mqh = t >> 8;
        const float2* arow = sA + (b*16 + ml)*33;
        float fr[4], fi[4];
        #pragma unroll
        for (int k=0;k<4;k++){fr[k]=0.f; fi[k]=0.f;}
        #pragma unroll
        for (int c0 = 0; c0 < 8; c0++) {
            zp[c0*512] = z4;                     // interleaved fill (8 total)
            float2 a0 = arow[c0], a1 = arow[c0+8], a2 = arow[c0+16], a3 = arow[c0+24];
            float2 u;
            if (r == 0)      u = make_float2(a0.x+a1.x+a2.x+a3.x, a0.y+a1.y+a2.y+a3.y);
            else if (r == 2) u = make_float2(a0.x-a1.x+a2.x-a3.x, a0.y-a1.y+a2.y-a3.y);
            else {
                float pr=a0.x-a2.x, pi=a0.y-a2.y, qr=a1.x-a3.x, qi=a1.y-a3.y;
                if (r == 1) u = make_float2(pr+qi, pi-qr);   // p - i q
                else        u = make_float2(pr-qi, pi+qr);   // p + i q
            }
            #pragma unroll
            for (int k=0;k<4;k++) {
                int i = 4*(mqh*4 + k) + r;
                float2 w = tw[(i*c0) & 31];      // e^{-i}: u*(cw - i sw)
                fr[k] += u.x*w.x + u.y*w.y;
                fi[k] += u.y*w.x - u.x*w.y;
            }
        }
        float2* frow = sF + (b*16 + ml)*33;
        #pragma unroll
        for (int k=0;k<4;k++)
            frow[4*(mqh*4 + k) + r] = make_float2(fr[k], fi[k]);
    }
    __syncthreads();

    // stage 2: channel mix. thread = (ml, o); weights loaded once, 4 b reuse.
    {
        int ml = t & 15, o = t >> 4;
        float r0=0,i0=0,r1=0,i1=0,r2=0,i2=0,r3=0,i3=0;
        const float* wrp = wr_g + (size_t)o*4096 + m0 + ml;
        const float* wip = wi_g + (size_t)o*4096 + m0 + ml;
        #pragma unroll 2
        for (int i = 0; i < 32; i++) {
            float wr = wrp[(size_t)i*131072];
            float wi = wip[(size_t)i*131072];
            float2 f0 = sF[( 0 + ml)*33 + i];
            float2 f1 = sF[(16 + ml)*33 + i];
            float2 f2 = sF[(32 + ml)*33 + i];
            float2 f3 = sF[(48 + ml)*33 + i];
            r0 += f0.x*wr - f0.y*wi;  i0 += f0.x*wi + f0.y*wr;
            r1 += f1.x*wr - f1.y*wi;  i1 += f1.x*wi + f1.y*wr;
            r2 += f2.x*wr - f2.y*wi;  i2 += f2.x*wi + f2.y*wr;
            r3 += f3.x*wr - f3.y*wi;  i3 += f3.x*wi + f3.y*wr;
        }
        sG[( 0 + ml)*33 + o] = make_float2(r0, i0);
        sG[(16 + ml)*33 + o] = make_float2(r1, i1);
        sG[(32 + ml)*33 + o] = make_float2(r2, i2);
        sG[(48 + ml)*33 + o] = make_float2(r3, i3);
    }
    __syncthreads();

    // stage 3: inverse DFT over o -> c (32 -> 32), radix-4, scaled.
    {
        int r = t & 3, ml = (t >> 2) & 15, b = (t >> 6) & 3, mqh = t >> 8;
        const float2* grow = sG + (b*16 + ml)*33;
        float cr[4], ci[4];
        #pragma unroll
        for (int k=0;k<4;k++){cr[k]=0.f; ci[k]=0.f;}
        #pragma unroll
        for (int o0 = 0; o0 < 8; o0++) {
            float2 g0 = grow[o0], g1 = grow[o0+8], g2 = grow[o0+16], g3 = grow[o0+24];
            float2 u;
            if (r == 0)      u = make_float2(g0.x+g1.x+g2.x+g3.x, g0.y+g1.y+g2.y+g3.y);
            else if (r == 2) u = make_float2(g0.x-g1.x+g2.x-g3.x, g0.y-g1.y+g2.y-g3.y);
            else {
                float pr=g0.x-g2.x, pi=g0.y-g2.y, qr=g1.x-g3.x, qi=g1.y-g3.y;
                if (r == 1) u = make_float2(pr-qi, pi+qr);   // p + i q
                else        u = make_float2(pr+qi, pi-qr);   // p - i q
            }
            #pragma unroll
            for (int k=0;k<4;k++) {
                int c = 4*(mqh*4 + k) + r;
                float2 w = tw[(c*o0) & 31];      // e^{+i}: u*(cw + i sw)
                cr[k] += u.x*w.x - u.y*w.y;
                ci[k] += u.x*w.y + u.y*w.x;
            }
        }
        float2* dst = g_A5 + ((size_t)(b*4096 + m0 + ml))*32;
        #pragma unroll
        for (int k=0;k<4;k++)
            dst[4*(mqh*4 + k) + r] = make_float2(cr[k]*SCALE, ci[k]*SCALE);
    }
}

// ============================================================================
// Kernel C: inverse DFT over ky (16->64) and kz (16->64 real), radix-4 output
// side. Block = (b, Xs, cg of 8 channels), 512 threads, __launch_bounds__
// (512,2): caps regs at 64 so TWO CTAs fit per SM (smem 2x80.5KB < 228KB),
// making grid 256 a single wave (was 1.73 waves at 1 CTA/SM).
// Carries 33% of the zero-fill (16 STG.128/thread) in stage 2's yy-loop.
// ============================================================================
__global__ __launch_bounds__(512, 2) void kC(float* __restrict__ out) {
    __shared__ float2 sIn[16*16*8];   // [ky][kz][c]
    __shared__ float2 t1[64*128];     // [y][kz*8+c]
    __shared__ float2 tw[64];
    int bid = blockIdx.x;             // b*64 + Xs*4 + cg
    int cg = bid & 3;
    int Xs = (bid >> 2) & 15;
    int b  = bid >> 6;
    int t = threadIdx.x;
    if (t < 64) {
        double ang = 2.0*PI_D*(double)t/64.0;
        tw[t] = make_float2((float)cos(ang), (float)sin(ang));
    }
    #pragma unroll
    for (int r = 0; r < 4; r++) {
        int idx = t + r*512;
        int c = idx & 7, kz = (idx >> 3) & 15, ky = idx >> 7;
        sIn[idx] = g_A5[((size_t)(b*4096 + Xs*256 + ky*16 + kz))*32 + cg*8 + c];
    }
    __syncthreads();

    // fill share: g in [4194304, 6291456), 8192 f4/block
    float4* zp = fill_ptr(out, 4194304L + (long)bid * 8192, t);
    const float4 z4 = make_float4(0.f, 0.f, 0.f, 0.f);

    // ---- stage 1: inverse ky-DFT (16 -> 64), output radix-4.
    {
        int c = t & 7, kz = (t >> 3) & 15, yq = t >> 7;
        float akr[16], aki[16];
        #pragma unroll
        for (int k = 0; k < 16; k++) {
            float2 a = sIn[(k*16 + kz)*8 + c];
            akr[k] = a.x; aki[k] = a.y;
        }
        #pragma unroll
        for (int j = 0; j < 4; j++) {
            int y0 = yq*4 + j;
            float Tr[4], Ti[4];
            #pragma unroll
            for (int r = 0; r < 4; r++) {
                float trr = 0.f, tii = 0.f;
                #pragma unroll
                for (int m = 0; m < 4; m++) {
                    int k = 4*m + r;
                    float2 w = tw[(k*y0)&63];    // e^{+i}
                    trr += akr[k]*w.x - aki[k]*w.y;
                    tii += akr[k]*w.y + aki[k]*w.x;
                }
                Tr[r] = trr; Ti[r] = tii;
            }
            float Er=Tr[0]+Tr[2], Ei=Ti[0]+Ti[2];
            float Fr=Tr[0]-Tr[2], Fi=Ti[0]-Ti[2];
            float Gr=Tr[1]+Tr[3], Gi=Ti[1]+Ti[3];
            float Hr=Tr[1]-Tr[3], Hi=Ti[1]-Ti[3];
            t1[(y0   )*128 + kz*8 + c] = make_float2(Er+Gr, Ei+Gi);  // p=0
            t1[(y0+16)*128 + kz*8 + c] = make_float2(Fr-Hi, Fi+Hr);  // p=1
            t1[(y0+32)*128 + kz*8 + c] = make_float2(Er-Gr, Ei-Gi);  // p=2
            t1[(y0+48)*128 + kz*8 + c] = make_float2(Fr+Hi, Fi-Hr);  // p=3
        }
    }
    __syncthreads();

    // ---- stage 2: inverse kz-DFT (16 -> 64), real part, output radix-4.
    {
        int c = t & 7, z0 = (t >> 3) & 15, yq = t >> 7;
        float cwv[16], swv[16];
        #pragma unroll
        for (int k = 0; k < 16; k++) {
            float2 w = tw[(k*z0)&63];
            cwv[k] = w.x; swv[k] = w.y;
        }
        float* dst = out + ((((size_t)b*64 + Xs)*64)*64)*32 + (size_t)z0*32 + cg*8 + c;
        for (int l = 0; l < 16; l++) {
            int yy = yq*16 + l;
            zp[l*512] = z4;                      // interleaved fill (16 total)
            float t0r=0.f, t2r=0.f, t1r=0.f, t1i=0.f, t3r=0.f, t3i=0.f;
            #pragma unroll
            for (int m = 0; m < 4; m++) {
                { int k=4*m;   float2 a=t1[yy*128+k*8+c]; t0r += a.x*cwv[k]-a.y*swv[k]; }
                { int k=4*m+2; float2 a=t1[yy*128+k*8+c]; t2r += a.x*cwv[k]-a.y*swv[k]; }
                { int k=4*m+1; float2 a=t1[yy*128+k*8+c]; t1r += a.x*cwv[k]-a.y*swv[k];
                                                          t1i += a.x*swv[k]+a.y*cwv[k]; }
                { int k=4*m+3; float2 a=t1[yy*128+k*8+c]; t3r += a.x*cwv[k]-a.y*swv[k];
                                                          t3i += a.x*swv[k]+a.y*cwv[k]; }
            }
            float t02p=t0r+t2r, t02m=t0r-t2r, t13p=t1r+t3r, h=t1i-t3i;
            size_t base = (size_t)yy*2048;
            dst[base        ] = t02p + t13p;   // z = z0
            dst[base +  512 ] = t02m - h;      // z = z0+16
            dst[base + 1024 ] = t02p - t13p;   // z = z0+32
            dst[base + 1536 ] = t02m + h;      // z = z0+48
        }
    }
}

extern "C" void kernel_launch(void* const* d_in, const int* in_sizes, int n_in,
                              void* d_out, int out_size) {
    const float* x  = (const float*)d_in[0];
    const float* wr = (const float*)d_in[1];
    const float* wi = (const float*)d_in[2];
    float* out = (float*)d_out;

    kA<<<256, 512>>>(x, out);        // forward z,y DFT + 50% fill
    kB<<<256, 512>>>(wr, wi, out);   // c-DFT (r4) + mix + inv o-DFT (r4) + 17% fill
    kC<<<256, 512>>>(out);           // inverse ky,kz DFT + 33% fill (2 CTA/SM)
}